// round 3
// baseline (speedup 1.0000x reference)
#include <cuda_runtime.h>
#include <cstdint>

#define LL 50          // labels + stop + start
#define LP 64          // padded row
#define NB 512
#define TT 1024
#define STOPI 48
#define STARTI 49
#define NEGV (-10000.0f)

// Scratch: Viterbi carry history, padded rows. hist row (b*TT + t) = vit after step t.
__device__ float g_hist[(size_t)NB * TT * LP];   // 134 MB, zero-init
__device__ int   g_order[NB];

// ---------------------------------------------------------------------------
// Pre-kernel: LPT order (descending len, stable by index)
// ---------------------------------------------------------------------------
__global__ void order_kernel(const int* __restrict__ lens) {
    __shared__ int sl[NB];
    int i = threadIdx.x;
    sl[i] = lens[i];
    __syncthreads();
    int li = sl[i];
    int r = 0;
#pragma unroll 8
    for (int j = 0; j < NB; j++) {
        int lj = sl[j];
        r += (lj > li) || (lj == li && j < i);
    }
    g_order[r] = i;
}

// Monotonic bijection float -> uint32 (order-preserving, tie-exact)
__device__ __forceinline__ unsigned mono(float f) {
    unsigned u = __float_as_uint(f);
    return u ^ ((unsigned)(((int)u) >> 31) | 0x80000000u);
}

// ---------------------------------------------------------------------------
// Main kernel: one block (64 threads) per batch element.
//  Phase 1 (forward, len_b steps): thread `to` computes
//     vt_max[to] = max_from(vit[from] + T[to][from])   (max only, no argmax)
//  storing the post-step vit into g_hist.
//  Phase 2 (backward, warp 0): recompute the single visited argmax per step.
// ---------------------------------------------------------------------------
__global__ __launch_bounds__(64) void crf_kernel(
    const float* __restrict__ feats,
    const int*   __restrict__ lens,
    const float* __restrict__ trans,
    float*       __restrict__ out)
{
    __shared__ float  Ts[LL * LP];                    // transitions, padded cols = NEG
    __shared__ float4 vit4[2][LP / 4];                // double-buffered vit
    __shared__ __align__(16) float ring[16 * LP];     // backward prefetch ring

    const int tid = threadIdx.x;
    const int b   = g_order[blockIdx.x];
    const int len = lens[b];

    // Load transitions into shared (padded with NEG)
    for (int idx = tid; idx < LL * LP; idx += 64) {
        int row = idx >> 6, f = idx & 63;
        Ts[idx] = (f < LL) ? trans[row * LL + f] : NEGV;
    }
    float* vs = (float*)vit4;
    {
        int l = tid;                                   // 0..63
        vs[0 * LP + l] = (l == STARTI) ? 0.0f : NEGV;  // vit0
        vs[1 * LP + l] = NEGV;                         // padding persists (stores predicated to<50)
    }
    __syncthreads();

    const int to  = tid;
    const int toc = (to < LL) ? to : (LL - 1);

    // This thread's transition row in registers (52 for float4 coverage)
    float Trow[52];
#pragma unroll
    for (int j = 0; j < 52; j++) Trow[j] = Ts[toc * LP + j];
    const float tstop = Ts[STOPI * LP + toc];

    const float* frow = feats + (size_t)b * TT * LL + toc;
    float*       hrow = g_hist + (size_t)b * TT * LP + to;

    // Logit prefetch pipeline (distance 2)
    float lg0 = frow[0];
    float lg1 = (len > 1) ? frow[LL] : lg0;

    int p = 0;
    for (int t = 0; t < len; t++) {
        float logit = lg0;
        lg0 = lg1;
        int tn = t + 2; if (tn > len - 1) tn = len - 1;
        lg1 = frow[(size_t)tn * LL];

        const float4* vb = &vit4[p][0];
        float m0 = -3.0e38f, m1 = m0, m2 = m0, m3 = m0;
#pragma unroll
        for (int j4 = 0; j4 < 13; j4++) {
            float4 v = vb[j4];                         // broadcast LDS.128
            m0 = fmaxf(m0, v.x + Trow[4 * j4 + 0]);
            m1 = fmaxf(m1, v.y + Trow[4 * j4 + 1]);
            m2 = fmaxf(m2, v.z + Trow[4 * j4 + 2]);
            m3 = fmaxf(m3, v.w + Trow[4 * j4 + 3]);
        }
        float vt = fmaxf(fmaxf(m0, m1), fmaxf(m2, m3));
        float vn = vt + logit;                         // same assoc. order as reference
        if (t == len - 1) vn += tstop;                 // stop transition at c==1
        if (to < LL) {
            vs[(p ^ 1) * LP + to] = vn;
            hrow[(size_t)t * LP] = vn;                 // hist[t+1] = carry for step t+1
        }
        __syncthreads();
        p ^= 1;
    }
    __syncthreads();

    // ---------------- Backward: warp 0 only ----------------
    if (tid >= 32) return;
    const int f = tid;
    float* vfin = &vs[p * LP];
    float* pout = out + NB + (size_t)b * TT;

    // scores / idx from final vit (exact max+first-argmax via monotonic keys)
    {
        unsigned k1 = mono(vfin[f]);
        unsigned k2 = (f < LL - 32) ? mono(vfin[32 + f]) : 0u;
        unsigned wm = __reduce_max_sync(0xFFFFFFFFu, k1 > k2 ? k1 : k2);
        unsigned b1 = __ballot_sync(0xFFFFFFFFu, k1 == wm);
        unsigned b2 = __ballot_sync(0xFFFFFFFFu, (k2 == wm) && (f < LL - 32));
        int idx = b1 ? (__ffs(b1) - 1) : (31 + __ffs(b2));
        unsigned su = (wm & 0x80000000u) ? (wm ^ 0x80000000u) : ~wm;
        if (f == 0) {
            out[b] = __uint_as_float(su);              // score
            pout[TT - 1] = (float)idx;                 // last path entry
        }
        // backtrace chase
        int i = idx;
        const float* hbase = g_hist + (size_t)b * TT * LP;
        uint32_t ring_base = (uint32_t)__cvta_generic_to_shared(ring);
        const int S = TT - 1;                          // steps t = 1023 .. 1

        // row for step s: carry_t with t = 1023-s, row index min(t,len)-1
        auto row_off = [&](int s) -> size_t {
            int t = (TT - 1) - s;
            int k = t < len ? t : len;
            return (size_t)(k - 1) * LP;
        };
        // prefill prefetch (distance 12)
        for (int s = 0; s < 12; s++) {
            if (f < 16) {
                const float* gp = hbase + row_off(s) + f * 4;
                uint32_t sa = ring_base + (((s & 15) * LP + f * 4) * 4);
                asm volatile("cp.async.cg.shared.global [%0], [%1], 16;\n" :: "r"(sa), "l"(gp));
            }
            asm volatile("cp.async.commit_group;\n");
        }
        for (int s = 0; s < S; s++) {
            int t = (TT - 1) - s;
            if (s + 12 >= S) { asm volatile("cp.async.wait_group 0;\n" ::: "memory"); }
            else            { asm volatile("cp.async.wait_group 11;\n" ::: "memory"); }
            __syncwarp();
            const float* rr = &ring[(s & 15) * LP];
            float c1 = rr[f]      + Ts[i * LP + f];
            float c2 = rr[32 + f] + Ts[i * LP + 32 + f];
            unsigned q1 = mono(c1);
            unsigned q2 = (f < LL - 32) ? mono(c2) : 0u;
            unsigned qm = __reduce_max_sync(0xFFFFFFFFu, q1 > q2 ? q1 : q2);
            unsigned a1 = __ballot_sync(0xFFFFFFFFu, q1 == qm);
            unsigned a2 = __ballot_sync(0xFFFFFFFFu, (q2 == qm) && (f < LL - 32));
            int ni = a1 ? (__ffs(a1) - 1) : (31 + __ffs(a2));
            if (f == 0) pout[t - 1] = (float)ni;       // paths[t-1] = back_seq[t]
            i = ni;
            __syncwarp();                              // all lanes done with slot s-? before reuse
            int sp = s + 12;
            if (sp < S) {
                if (f < 16) {
                    const float* gp = hbase + row_off(sp) + f * 4;
                    uint32_t sa = ring_base + (((sp & 15) * LP + f * 4) * 4);
                    asm volatile("cp.async.cg.shared.global [%0], [%1], 16;\n" :: "r"(sa), "l"(gp));
                }
            }
            asm volatile("cp.async.commit_group;\n");
        }
    }
}

extern "C" void kernel_launch(void* const* d_in, const int* in_sizes, int n_in,
                              void* d_out, int out_size) {
    const float* feats = (const float*)d_in[0];
    const int*   lens  = (const int*)d_in[1];
    const float* trans = (const float*)d_in[2];
    float* out = (float*)d_out;
    (void)in_sizes; (void)n_in; (void)out_size;

    order_kernel<<<1, NB>>>(lens);
    crf_kernel<<<NB, 64>>>(feats, lens, trans, out);
}

// round 10
// speedup vs baseline: 1.8151x; 1.8151x over previous
#include <cuda_runtime.h>
#include <cstdint>

#define LL 50          // labels + stop + start
#define LP 64          // padded row
#define NB 512
#define TT 1024
#define STOPI 48
#define STARTI 49
#define NEGV (-10000.0f)

typedef unsigned long long u64;

// Scratch: Viterbi carry history, padded rows. hist row (b*TT + t) = vit after step t.
__device__ float g_hist[(size_t)NB * TT * LP];   // 134 MB
__device__ int   g_order[NB];

// ---------------------------------------------------------------------------
// Pre-kernel: LPT order (descending len, stable by index)
// ---------------------------------------------------------------------------
__global__ void order_kernel(const int* __restrict__ lens) {
    __shared__ int sl[NB];
    int i = threadIdx.x;
    sl[i] = lens[i];
    __syncthreads();
    int li = sl[i];
    int r = 0;
#pragma unroll 8
    for (int j = 0; j < NB; j++) {
        int lj = sl[j];
        r += (lj > li) || (lj == li && j < i);
    }
    g_order[r] = i;
}

// Monotonic bijection float -> uint32 (order-preserving, tie-exact)
__device__ __forceinline__ unsigned mono(float f) {
    unsigned u = __float_as_uint(f);
    return u ^ ((unsigned)(((int)u) >> 31) | 0x80000000u);
}

// Packed f32x2 add (sm_100+): elementwise IEEE add on a register pair.
__device__ __forceinline__ u64 add2(u64 a, u64 b) {
    u64 r; asm("add.rn.f32x2 %0, %1, %2;" : "=l"(r) : "l"(a), "l"(b)); return r;
}

// ---------------------------------------------------------------------------
// Main kernel: one block (64 threads = 2 warps) per batch element.
// Forward: thread `to` computes max over `from`; adds packed (FADD2), maxes
//          scalar (FMNMX); logits streamed via a cp.async ring (dist 8).
// Backward: frozen-region pointers via precomputed map P* with fixed-point
//           early exit; real region recomputed with a cp.async hist ring.
// ---------------------------------------------------------------------------
__global__ __launch_bounds__(64) void crf_kernel(
    const float* __restrict__ feats,
    const int*   __restrict__ lens,
    const float* __restrict__ trans,
    float*       __restrict__ out)
{
    __shared__ float  Ts[LL * LP];                    // transitions, padded cols = NEG
    __shared__ float4 vit4[2][LP / 4];                // double-buffered vit
    __shared__ __align__(16) float ring[16 * LP];     // backward hist prefetch ring
    __shared__ __align__(16) float lring[16 * LP];    // forward logit ring
    __shared__ int sP[LP];                            // frozen-region pointer map P*

    const int tid = threadIdx.x;
    const int b   = g_order[blockIdx.x];
    const int len = lens[b];

    // Load transitions into shared (padded with NEG)
    for (int idx = tid; idx < LL * LP; idx += 64) {
        int row = idx >> 6, f = idx & 63;
        Ts[idx] = (f < LL) ? trans[row * LL + f] : NEGV;
    }
    float* vs = (float*)vit4;
    {
        int l = tid;
        vs[0 * LP + l] = (l == STARTI) ? 0.0f : NEGV;
        vs[1 * LP + l] = NEGV;                         // padding persists
    }

    const int to  = tid;
    const int toc = (to < LL) ? to : (LL - 1);
    const float* frow = feats + (size_t)b * TT * LL + toc;
    float*       hrow = g_hist + (size_t)b * TT * LP + to;

    // Prologue: logit cp.async ring, slots 0..7 (distance 8, depth 16)
    const uint32_t lrbase = (uint32_t)__cvta_generic_to_shared(lring);
    for (int k = 0; k < 8; k++) {
        int tc = k; if (tc > len - 1) tc = len - 1;
        const float* gp = frow + (size_t)tc * LL;
        uint32_t sa = lrbase + (((k & 15) * LP + tid) * 4);
        asm volatile("cp.async.ca.shared.global [%0], [%1], 4;\n" :: "r"(sa), "l"(gp));
        asm volatile("cp.async.commit_group;\n" ::: "memory");
    }
    __syncthreads();

    // This thread's transition row, packed as 26 f32x2 pairs
    u64 T2[26];
#pragma unroll
    for (int j = 0; j < 26; j++) T2[j] = ((const u64*)&Ts[toc * LP])[j];
    const float tstop = Ts[STOPI * LP + toc];

    int p = 0;
    for (int t = 0; t < len; t++) {
        const ulonglong2* vb = (const ulonglong2*)&vit4[p][0];
        float m0 = -3.0e38f, m1 = m0, m2 = m0, m3 = m0;
#pragma unroll
        for (int j = 0; j < 13; j++) {
            ulonglong2 w = vb[j];                      // LDS.128 broadcast
            union { u64 u; float2 f; } s0, s1;
            s0.u = add2(w.x, T2[2 * j]);               // packed adds (FADD2)
            s1.u = add2(w.y, T2[2 * j + 1]);
            m0 = fmaxf(m0, s0.f.x);                    // scalar FMNMX, 4-way ILP
            m1 = fmaxf(m1, s0.f.y);
            m2 = fmaxf(m2, s1.f.x);
            m3 = fmaxf(m3, s1.f.y);
        }
        float vt = fmaxf(fmaxf(m0, m1), fmaxf(m2, m3));

        asm volatile("cp.async.wait_group 7;\n" ::: "memory");
        float logit = lring[(t & 15) * LP + tid];
        float vn = vt + logit;                         // same assoc. order as reference
        if (t == len - 1) vn += tstop;                 // stop transition at c==1
        if (to < LL) {
            vs[(p ^ 1) * LP + to] = vn;
            hrow[(size_t)t * LP] = vn;                 // hist[t] = carry after step t
        }
        // prefetch logit for step t+8 into slot (t+8)&15
        {
            int tc = t + 8; if (tc > len - 1) tc = len - 1;
            const float* gp = frow + (size_t)tc * LL;
            uint32_t sa = lrbase + ((((t + 8) & 15) * LP + tid) * 4);
            asm volatile("cp.async.ca.shared.global [%0], [%1], 4;\n" :: "r"(sa), "l"(gp));
            asm volatile("cp.async.commit_group;\n" ::: "memory");
        }
        __syncthreads();
        p ^= 1;
    }
    asm volatile("cp.async.wait_group 0;\n" ::: "memory");  // drain logit groups

    // ---------------- Frozen pointer map P* (all threads, once) -------------
    float* vfin = &vs[p * LP];
    {
        float best = -3.0e38f; int bi = 0;
#pragma unroll
        for (int j = 0; j < 26; j++) {
            union { u64 u; float2 f; } tt; tt.u = T2[j];
            float c0 = vfin[2 * j]     + tt.f.x;
            if (c0 > best) { best = c0; bi = 2 * j; }
            float c1 = vfin[2 * j + 1] + tt.f.y;
            if (c1 > best) { best = c1; bi = 2 * j + 1; }
        }
        if (to < LL) sP[to] = bi;                      // first-tie == reference argmax
    }
    __syncthreads();

    // ---------------- Backward: warp 0 only ----------------
    if (tid >= 32) return;
    const int f = tid;
    float* pout = out + NB + (size_t)b * TT;

    // scores / idx from final vit (exact max+first-argmax via monotonic keys)
    unsigned k1 = mono(vfin[f]);
    unsigned k2 = (f < LL - 32) ? mono(vfin[32 + f]) : 0u;
    unsigned wm = __reduce_max_sync(0xFFFFFFFFu, k1 > k2 ? k1 : k2);
    unsigned b1 = __ballot_sync(0xFFFFFFFFu, k1 == wm);
    unsigned b2 = __ballot_sync(0xFFFFFFFFu, (k2 == wm) && (f < LL - 32));
    int idx = b1 ? (__ffs(b1) - 1) : (31 + __ffs(b2));
    unsigned su = (wm & 0x80000000u) ? (wm ^ 0x80000000u) : ~wm;
    if (f == 0) {
        out[b] = __uint_as_float(su);                  // score
        pout[TT - 1] = (float)idx;                     // last path entry
    }

    int i = idx;

    // Frozen region: steps t in [len, 1023] all use P* (carry is frozen).
    if (len < TT) {
        int fh = len - 1, ii = i;
        if (f == 0) {
            int t = TT - 1, cur = i;
            for (; t >= len; --t) {
                int ni = sP[cur];
                pout[t - 1] = (float)ni;
                if (ni == cur) { --t; break; }         // fixed point: rest is constant
                cur = ni;
            }
            fh = t; ii = cur;
        }
        fh = __shfl_sync(0xFFFFFFFFu, fh, 0);
        i  = __shfl_sync(0xFFFFFFFFu, ii, 0);
        for (int t = fh - f; t >= len; t -= 32)        // parallel constant fill
            pout[t - 1] = (float)i;
    }

    // Real region: steps t = len-1 .. 1, recompute argmax from hist rows.
    const int S = len - 1;
    if (S > 0) {
        const float* hbase = g_hist + (size_t)b * TT * LP;
        uint32_t ring_base = (uint32_t)__cvta_generic_to_shared(ring);
        // step s looks at carry after step (len-2-s): hist row (len-2-s)
        for (int s = 0; s < 12; s++) {
            int k = len - 2 - s; if (k < 0) k = 0;
            if (f < 16) {
                const float* gp = hbase + (size_t)k * LP + f * 4;
                uint32_t sa = ring_base + (((s & 15) * LP + f * 4) * 4);
                asm volatile("cp.async.cg.shared.global [%0], [%1], 16;\n" :: "r"(sa), "l"(gp));
            }
            asm volatile("cp.async.commit_group;\n" ::: "memory");
        }
        for (int s = 0; s < S; s++) {
            int t = len - 1 - s;
            if (s + 12 >= S) { asm volatile("cp.async.wait_group 0;\n" ::: "memory"); }
            else            { asm volatile("cp.async.wait_group 11;\n" ::: "memory"); }
            __syncwarp();
            const float* rr = &ring[(s & 15) * LP];
            float c1 = rr[f]      + Ts[i * LP + f];
            float c2 = rr[32 + f] + Ts[i * LP + 32 + f];
            unsigned q1 = mono(c1);
            unsigned q2 = (f < LL - 32) ? mono(c2) : 0u;
            unsigned qm = __reduce_max_sync(0xFFFFFFFFu, q1 > q2 ? q1 : q2);
            unsigned a1 = __ballot_sync(0xFFFFFFFFu, q1 == qm);
            unsigned a2 = __ballot_sync(0xFFFFFFFFu, (q2 == qm) && (f < LL - 32));
            int ni = a1 ? (__ffs(a1) - 1) : (31 + __ffs(a2));
            if (f == 0) pout[t - 1] = (float)ni;
            i = ni;
            __syncwarp();
            int sp = s + 12;
            if (sp < S) {
                int k = len - 2 - sp;
                if (f < 16) {
                    const float* gp = hbase + (size_t)k * LP + f * 4;
                    uint32_t sa = ring_base + (((sp & 15) * LP + f * 4) * 4);
                    asm volatile("cp.async.cg.shared.global [%0], [%1], 16;\n" :: "r"(sa), "l"(gp));
                }
            }
            asm volatile("cp.async.commit_group;\n" ::: "memory");
        }
    }
}

extern "C" void kernel_launch(void* const* d_in, const int* in_sizes, int n_in,
                              void* d_out, int out_size) {
    const float* feats = (const float*)d_in[0];
    const int*   lens  = (const int*)d_in[1];
    const float* trans = (const float*)d_in[2];
    float* out = (float*)d_out;
    (void)in_sizes; (void)n_in; (void)out_size;

    order_kernel<<<1, NB>>>(lens);
    crf_kernel<<<NB, 64>>>(feats, lens, trans, out);
}